// round 15
// baseline (speedup 1.0000x reference)
#include <cuda_runtime.h>
#include <cuda_bf16.h>
#include <cstdint>

// Problem dims (fixed by the dataset)
#define TT 512
#define NN 64
#define DD 1024
#define HH 1024
#define GG 4096        // 4*H

#define NBLK 128       // persistent blocks, 1/SM
#define KS 8           // K splits for recurrent GEMM
#define KC (HH / KS)   // 128
#define CGRP 16        // column groups
#define CW (GG / CGRP) // 256 cols per group

// recurrence smem (bytes): Wh^T hi/lo [256][136] bf16 + h hi/lo [64][136] bf16
#define WST 136
#define WHS_HI_OFF 0
#define WHS_LO_OFF (256 * WST * 2)                    // 69632
#define ASH_HI_OFF (2 * 256 * WST * 2)                // 139264
#define ASH_LO_OFF (ASH_HI_OFF + 64 * WST * 2)        // 156672
#define LSTM_SMEM  (ASH_LO_OFF + 64 * WST * 2)        // 174080

// ---- device scratch (allocation-free per harness rules) ----
__device__ float g_xw[(size_t)TT * NN * GG];        // (T*N, 4H) x@Wx + b
__device__ float g_part[KS][NN * GG];               // split-K partials of h@Wh
__device__ __nv_bfloat16 g_h_hi[NN * HH];           // hidden state, hi plane
__device__ __nv_bfloat16 g_h_lo[NN * HH];           // hidden state, lo plane
__device__ unsigned g_c1[16 * 64];                  // tree barrier level-1 (256B apart)
__device__ unsigned g_croot;
__device__ unsigned g_gen;

// bf16 hi/lo split operands for the xW tensor GEMM (k-contiguous rows)
__device__ __nv_bfloat16 g_xa_hi[(size_t)TT * NN * DD];   // A[m][k], m = t*64+n
__device__ __nv_bfloat16 g_xa_lo[(size_t)TT * NN * DD];
__device__ __nv_bfloat16 g_wxt_hi[(size_t)GG * DD];       // B[g][k] = Wx[k][g]
__device__ __nv_bfloat16 g_wxt_lo[(size_t)GG * DD];

// ---------------------------------------------------------------------------
// helpers
// ---------------------------------------------------------------------------
__device__ __forceinline__ float sigm(float x) { return 1.f / (1.f + __expf(-x)); }
__device__ __forceinline__ float tanh_(float x) { return 2.f / (1.f + __expf(-2.f * x)) - 1.f; }

__device__ __forceinline__ unsigned atom_add_acqrel(unsigned* p) {
    unsigned old;
    asm volatile("atom.add.acq_rel.gpu.global.u32 %0, [%1], 1;"
                 : "=r"(old) : "l"(p) : "memory");
    return old;
}

// Two-level tree barrier: 16 groups x 8 blocks -> root of 16.
// Level-1 counters are 256B apart (distinct LTS banks) so arrivals parallelize.
__device__ __forceinline__ void grid_sync() {
    __syncthreads();
    if (threadIdx.x == 0) {
        unsigned my;
        asm volatile("ld.acquire.gpu.global.u32 %0, [%1];" : "=r"(my) : "l"(&g_gen));
        __threadfence();
        const int grp = blockIdx.x >> 3;   // 0..15
        if (atom_add_acqrel(&g_c1[grp << 6]) == 7) {
            g_c1[grp << 6] = 0;
            if (atom_add_acqrel(&g_croot) == 15) {
                g_croot = 0;
                asm volatile("st.release.gpu.global.u32 [%0], %1;"
                             :: "l"(&g_gen), "r"(my + 1));
            }
        }
        unsigned cur;
        do {
            asm volatile("ld.acquire.gpu.global.u32 %0, [%1];" : "=r"(cur) : "l"(&g_gen));
        } while (cur == my);
    }
    __syncthreads();
}

__device__ __forceinline__ uint32_t smem_u32(const void* p) {
    uint32_t a;
    asm("{ .reg .u64 t; cvta.to.shared.u64 t, %1; cvt.u32.u64 %0, t; }" : "=r"(a) : "l"(p));
    return a;
}

#define LDSM_X4(r0, r1, r2, r3, addr)                                           \
    asm volatile("ldmatrix.sync.aligned.m8n8.x4.shared.b16 {%0,%1,%2,%3}, [%4];" \
                 : "=r"(r0), "=r"(r1), "=r"(r2), "=r"(r3) : "r"(addr))

#define MMA_BF16(c, a0, a1, a2, a3, b0, b1)                                     \
    asm volatile("mma.sync.aligned.m16n8k16.row.col.f32.bf16.bf16.f32 "         \
                 "{%0,%1,%2,%3},{%4,%5,%6,%7},{%8,%9},{%0,%1,%2,%3};"           \
                 : "+f"(c[0]), "+f"(c[1]), "+f"(c[2]), "+f"(c[3])               \
                 : "r"(a0), "r"(a1), "r"(a2), "r"(a3), "r"(b0), "r"(b1))

// ---------------------------------------------------------------------------
// split kernels: fp32 -> bf16 hi + bf16 lo  (xW operands)
// ---------------------------------------------------------------------------
__global__ __launch_bounds__(256) void split_x(const float* __restrict__ x) {
    const int m = blockIdx.x;               // m = t*64 + n
    const int t = m >> 6, n = m & 63;
    const float* src = x + ((size_t)n * TT + t) * DD;
    const int d0 = threadIdx.x * 4;
    float4 v = *(const float4*)(src + d0);
    float f[4] = {v.x, v.y, v.z, v.w};
    ushort4 hi, lo;
    unsigned short* hp = &hi.x;
    unsigned short* lp = &lo.x;
    #pragma unroll
    for (int i = 0; i < 4; i++) {
        __nv_bfloat16 h = __float2bfloat16(f[i]);
        __nv_bfloat16 l = __float2bfloat16(f[i] - __bfloat162float(h));
        hp[i] = __bfloat16_as_ushort(h);
        lp[i] = __bfloat16_as_ushort(l);
    }
    size_t o = (size_t)m * DD + d0;
    *(ushort4*)&g_xa_hi[o] = hi;
    *(ushort4*)&g_xa_lo[o] = lo;
}

__global__ __launch_bounds__(256) void split_wx(const float* __restrict__ Wx) {
    __shared__ float tile[32][33];
    const int g0 = blockIdx.x * 32, k0 = blockIdx.y * 32;
    const int tx = threadIdx.x & 31, ty = threadIdx.x >> 5;   // 32 x 8
    #pragma unroll
    for (int j = 0; j < 4; j++)
        tile[ty + j * 8][tx] = Wx[(size_t)(k0 + ty + j * 8) * GG + g0 + tx];
    __syncthreads();
    #pragma unroll
    for (int j = 0; j < 4; j++) {
        float v = tile[tx][ty + j * 8];
        __nv_bfloat16 h = __float2bfloat16(v);
        __nv_bfloat16 l = __float2bfloat16(v - __bfloat162float(h));
        size_t o = (size_t)(g0 + ty + j * 8) * DD + k0 + tx;
        g_wxt_hi[o] = h;
        g_wxt_lo[o] = l;
    }
}

// ---------------------------------------------------------------------------
// xW GEMM on tensor cores (mma.sync bf16, 3-term hi/lo split).
// NEW vs R14: double-buffered smem staging (dynamic 80 KB), register
// prefetch of the next 32-k chunk overlapped with compute; 1 sync per chunk.
// ---------------------------------------------------------------------------
#define AST 40
#define XW_ARR  (128 * AST * 2)          // 10240 B per array
#define XW_BUF  (4 * XW_ARR)             // 40960 B per stage buffer
#define XW_SMEM (2 * XW_BUF)             // 81920 B

__global__ __launch_bounds__(256) void xw_mma(const float* __restrict__ b) {
    extern __shared__ char xsm[];
    const uint32_t sb = smem_u32(xsm);

    const int tid = threadIdx.x;
    const int wid = tid >> 5, lane = tid & 31;
    const int m0 = blockIdx.y * 128;
    const int g0 = blockIdx.x * 128;
    const int wm = (wid >> 2) * 64;
    const int wn = (wid & 3) * 32;

    float acc[4][4][4];
    #pragma unroll
    for (int i = 0; i < 4; i++)
        #pragma unroll
        for (int j = 0; j < 4; j++)
            #pragma unroll
            for (int q = 0; q < 4; q++) acc[i][j][q] = 0.f;

    const int sr = tid >> 1;
    const int sh = (tid & 1) * 16;
    const int so2 = (sr * AST + sh) * 2;   // byte offset within array

    const uint32_t a_off = (uint32_t)(wm + (lane & 15)) * (AST * 2) + ((lane >> 4) << 4);
    const uint32_t b_off = (uint32_t)(wn + ((lane >> 4) << 3) + (lane & 7)) * (AST * 2)
                           + (((lane >> 3) & 1) << 4);

    const __nv_bfloat16* srcs[4] = {
        g_xa_hi + (size_t)(m0 + sr) * DD + sh,
        g_xa_lo + (size_t)(m0 + sr) * DD + sh,
        g_wxt_hi + (size_t)(g0 + sr) * DD + sh,
        g_wxt_lo + (size_t)(g0 + sr) * DD + sh,
    };

    // prologue: load + store chunk 0 into buffer 0
    uint4 pre[4][2];
    #pragma unroll
    for (int a = 0; a < 4; a++) {
        pre[a][0] = *(const uint4*)(srcs[a]);
        pre[a][1] = *(const uint4*)(srcs[a] + 8);
    }
    #pragma unroll
    for (int a = 0; a < 4; a++) {
        char* dst = xsm + a * XW_ARR + so2;
        *(uint4*)dst = pre[a][0];
        *(uint4*)(dst + 16) = pre[a][1];
    }
    __syncthreads();

    for (int i = 0; i < 32; ++i) {
        const int cur = i & 1;
        const bool more = (i + 1 < 32);
        if (more) {
            const int k0 = (i + 1) * 32;
            #pragma unroll
            for (int a = 0; a < 4; a++) {
                pre[a][0] = *(const uint4*)(srcs[a] + k0);
                pre[a][1] = *(const uint4*)(srcs[a] + k0 + 8);
            }
        }

        const uint32_t base = sb + (uint32_t)cur * XW_BUF;
        const uint32_t ah_b = base, al_b = base + XW_ARR;
        const uint32_t bh_b = base + 2 * XW_ARR, bl_b = base + 3 * XW_ARR;

        #pragma unroll
        for (int ks = 0; ks < 32; ks += 16) {
            const uint32_t kb = (uint32_t)ks * 2;
            uint32_t bhf[4][2], blf[4][2];
            #pragma unroll
            for (int p = 0; p < 2; p++) {
                uint32_t r0, r1, r2, r3;
                uint32_t off = b_off + (uint32_t)(p * 16) * (AST * 2) + kb;
                LDSM_X4(r0, r1, r2, r3, bh_b + off);
                bhf[2 * p][0] = r0; bhf[2 * p][1] = r1;
                bhf[2 * p + 1][0] = r2; bhf[2 * p + 1][1] = r3;
                LDSM_X4(r0, r1, r2, r3, bl_b + off);
                blf[2 * p][0] = r0; blf[2 * p][1] = r1;
                blf[2 * p + 1][0] = r2; blf[2 * p + 1][1] = r3;
            }
            #pragma unroll
            for (int mt = 0; mt < 4; mt++) {
                uint32_t off = a_off + (uint32_t)(mt * 16) * (AST * 2) + kb;
                uint32_t ah0, ah1, ah2, ah3, al0, al1, al2, al3;
                LDSM_X4(ah0, ah1, ah2, ah3, ah_b + off);
                LDSM_X4(al0, al1, al2, al3, al_b + off);
                #pragma unroll
                for (int nt = 0; nt < 4; nt++) {
                    MMA_BF16(acc[mt][nt], ah0, ah1, ah2, ah3, bhf[nt][0], bhf[nt][1]);
                    MMA_BF16(acc[mt][nt], ah0, ah1, ah2, ah3, blf[nt][0], blf[nt][1]);
                    MMA_BF16(acc[mt][nt], al0, al1, al2, al3, bhf[nt][0], bhf[nt][1]);
                }
            }
        }

        if (more) {
            char* nb = xsm + (cur ^ 1) * XW_BUF + so2;
            #pragma unroll
            for (int a = 0; a < 4; a++) {
                *(uint4*)(nb + a * XW_ARR) = pre[a][0];
                *(uint4*)(nb + a * XW_ARR + 16) = pre[a][1];
            }
        }
        __syncthreads();
    }

    const int er = lane >> 2;
    const int ec = (lane & 3) * 2;
    #pragma unroll
    for (int mt = 0; mt < 4; mt++) {
        #pragma unroll
        for (int nt = 0; nt < 4; nt++) {
            const int col = g0 + wn + (nt >> 1) * 16 + (nt & 1) * 8 + ec;
            const float2 bias = *(const float2*)&b[col];
            const int row = m0 + wm + mt * 16 + er;
            float2 v0 = make_float2(acc[mt][nt][0] + bias.x, acc[mt][nt][1] + bias.y);
            float2 v1 = make_float2(acc[mt][nt][2] + bias.x, acc[mt][nt][3] + bias.y);
            *(float2*)&g_xw[(size_t)row * GG + col] = v0;
            *(float2*)&g_xw[(size_t)(row + 8) * GG + col] = v1;
        }
    }
}

// ---------------------------------------------------------------------------
// Persistent LSTM recurrence (R14 design + tree barrier).
// 128 blocks x 256 threads, 1 CTA/SM. Split-K=8, col-groups=16.
// Wh^T slice SMEM-resident bf16 hi/lo; h in GMEM as bf16 hi/lo planes.
// ---------------------------------------------------------------------------
__global__ void __launch_bounds__(256, 1) lstm_persistent(
    const float* __restrict__ h0,
    const float* __restrict__ Wh,
    float* __restrict__ out) {
    extern __shared__ char smc[];
    __nv_bfloat16* whs_hi = (__nv_bfloat16*)(smc + WHS_HI_OFF);   // [256][WST]
    __nv_bfloat16* whs_lo = (__nv_bfloat16*)(smc + WHS_LO_OFF);
    __nv_bfloat16* ash_hi = (__nv_bfloat16*)(smc + ASH_HI_OFF);   // [64][WST]
    __nv_bfloat16* ash_lo = (__nv_bfloat16*)(smc + ASH_LO_OFF);

    const int tid = threadIdx.x;
    const int blk = blockIdx.x;
    const int wid = tid >> 5, lane = tid & 31;
    const int cg = blk >> 3;           // 0..15 column group
    const int ks = blk & 7;            // 0..7  K split
    const int nc0 = cg * CW;
    const int kbase = ks * KC;
    const int wn = wid * 32;           // warp col offset (8 warps x 32 cols)

    // gate coords: 2 consecutive cells per thread
    const int ge = (blk * 256 + tid) * 2;
    const int gn = ge >> 10;
    const int gj = ge & 1023;

    // ---- one-time: Wh^T slice -> smem bf16 hi/lo, [col][k] stride WST ----
    for (int idx = tid; idx < CW * KC; idx += 256) {
        const int col = idx & 255;
        const int k = idx >> 8;
        float v = Wh[(size_t)(kbase + k) * GG + nc0 + col];
        __nv_bfloat16 h = __float2bfloat16(v);
        __nv_bfloat16 l = __float2bfloat16(v - __bfloat162float(h));
        whs_hi[col * WST + k] = h;
        whs_lo[col * WST + k] = l;
    }

    // ---- init h planes from h0 ----
    {
        float2 v = *(const float2*)&h0[ge];
        __nv_bfloat16 h0a = __float2bfloat16(v.x);
        __nv_bfloat16 h0b = __float2bfloat16(v.y);
        __nv_bfloat16 l0a = __float2bfloat16(v.x - __bfloat162float(h0a));
        __nv_bfloat16 l0b = __float2bfloat16(v.y - __bfloat162float(h0b));
        *(uint32_t*)&g_h_hi[ge] =
            (uint32_t)__bfloat16_as_ushort(h0a) | ((uint32_t)__bfloat16_as_ushort(h0b) << 16);
        *(uint32_t*)&g_h_lo[ge] =
            (uint32_t)__bfloat16_as_ushort(l0a) | ((uint32_t)__bfloat16_as_ushort(l0b) << 16);
    }
    float2 c = make_float2(0.f, 0.f);
    grid_sync();

    // stage coords: row = tid>>2 (0..63), kq = (tid&3)*32 elements
    const int s_row = tid >> 2;
    const int s_kq = (tid & 3) * 32;
    const __nv_bfloat16* hsrc_hi = g_h_hi + (size_t)s_row * HH + kbase + s_kq;
    const __nv_bfloat16* hsrc_lo = g_h_lo + (size_t)s_row * HH + kbase + s_kq;

    // ldmatrix offsets (bytes), stride WST*2 = 272
    const uint32_t ahi_b = smem_u32(ash_hi), alo_b = smem_u32(ash_lo);
    const uint32_t bhi_b = smem_u32(whs_hi), blo_b = smem_u32(whs_lo);
    const uint32_t a_off = (uint32_t)(lane & 15) * (WST * 2) + ((lane >> 4) << 4);
    const uint32_t b_off = (uint32_t)(wn + ((lane >> 4) << 3) + (lane & 7)) * (WST * 2)
                           + (((lane >> 3) & 1) << 4);

    for (int t = 0; t < TT; ++t) {
        // prefetch xw gate values (hidden behind MMA phase)
        float2 xg[4];
        {
            const float* xwt = g_xw + (size_t)t * NN * GG + (size_t)gn * GG + gj;
            #pragma unroll
            for (int g = 0; g < 4; g++) xg[g] = *(const float2*)(xwt + g * HH);
        }

        // ---------- stage: h slice -> smem (pure copy) ----------
        {
            __nv_bfloat16* dh = ash_hi + s_row * WST + s_kq;
            __nv_bfloat16* dl = ash_lo + s_row * WST + s_kq;
            #pragma unroll
            for (int i = 0; i < 4; ++i) {
                *(uint4*)(dh + i * 8) = *(const uint4*)(hsrc_hi + i * 8);
                *(uint4*)(dl + i * 8) = *(const uint4*)(hsrc_lo + i * 8);
            }
        }
        __syncthreads();

        // ---------- MMA phase: 64 x 32(warp) x 128, 3-term split ----------
        float acc[4][4][4];
        #pragma unroll
        for (int i = 0; i < 4; i++)
            #pragma unroll
            for (int j = 0; j < 4; j++)
                #pragma unroll
                for (int q = 0; q < 4; q++) acc[i][j][q] = 0.f;

        #pragma unroll
        for (int kk = 0; kk < 8; ++kk) {
            const uint32_t kb = (uint32_t)kk * 32;
            uint32_t bhf[4][2], blf[4][2];
            #pragma unroll
            for (int p = 0; p < 2; p++) {
                uint32_t r0, r1, r2, r3;
                uint32_t off = b_off + (uint32_t)(p * 16) * (WST * 2) + kb;
                LDSM_X4(r0, r1, r2, r3, bhi_b + off);
                bhf[2 * p][0] = r0; bhf[2 * p][1] = r1;
                bhf[2 * p + 1][0] = r2; bhf[2 * p + 1][1] = r3;
                LDSM_X4(r0, r1, r2, r3, blo_b + off);
                blf[2 * p][0] = r0; blf[2 * p][1] = r1;
                blf[2 * p + 1][0] = r2; blf[2 * p + 1][1] = r3;
            }
            #pragma unroll
            for (int mt = 0; mt < 4; mt++) {
                uint32_t off = a_off + (uint32_t)(mt * 16) * (WST * 2) + kb;
                uint32_t ah0, ah1, ah2, ah3, al0, al1, al2, al3;
                LDSM_X4(ah0, ah1, ah2, ah3, ahi_b + off);
                LDSM_X4(al0, al1, al2, al3, alo_b + off);
                #pragma unroll
                for (int nt = 0; nt < 4; nt++) {
                    MMA_BF16(acc[mt][nt], ah0, ah1, ah2, ah3, bhf[nt][0], bhf[nt][1]);
                    MMA_BF16(acc[mt][nt], ah0, ah1, ah2, ah3, blf[nt][0], blf[nt][1]);
                    MMA_BF16(acc[mt][nt], al0, al1, al2, al3, bhf[nt][0], bhf[nt][1]);
                }
            }
        }
        __syncthreads();   // ash reuse next step

        // ---------- store partial tile ----------
        {
            float* dst = g_part[ks];
            const int er = lane >> 2;
            const int ec = (lane & 3) * 2;
            #pragma unroll
            for (int mt = 0; mt < 4; mt++) {
                #pragma unroll
                for (int nt = 0; nt < 4; nt++) {
                    const int col = nc0 + wn + (nt >> 1) * 16 + (nt & 1) * 8 + ec;
                    const int row = mt * 16 + er;
                    *(float2*)&dst[(size_t)row * GG + col] =
                        make_float2(acc[mt][nt][0], acc[mt][nt][1]);
                    *(float2*)&dst[(size_t)(row + 8) * GG + col] =
                        make_float2(acc[mt][nt][2], acc[mt][nt][3]);
                }
            }
        }
        grid_sync();

        // ---------- gates: 2 cells per thread ----------
        {
            size_t bi = (size_t)gn * GG + gj;
            float2 pi = xg[0], pf = xg[1], po = xg[2], pg = xg[3];
            #pragma unroll
            for (int s = 0; s < KS; ++s) {
                const float* p = g_part[s];
                float2 v;
                v = *(const float2*)&p[bi];          pi.x += v.x; pi.y += v.y;
                v = *(const float2*)&p[bi + HH];     pf.x += v.x; pf.y += v.y;
                v = *(const float2*)&p[bi + 2 * HH]; po.x += v.x; po.y += v.y;
                v = *(const float2*)&p[bi + 3 * HH]; pg.x += v.x; pg.y += v.y;
            }
            float i0 = sigm(pi.x), f0 = sigm(pf.x), o0 = sigm(po.x), q0 = tanh_(pg.x);
            float i1 = sigm(pi.y), f1 = sigm(pf.y), o1 = sigm(po.y), q1 = tanh_(pg.y);
            c.x = f0 * c.x + i0 * q0;
            c.y = f1 * c.y + i1 * q1;
            float hv0 = o0 * tanh_(c.x);
            float hv1 = o1 * tanh_(c.y);

            __nv_bfloat16 hh0 = __float2bfloat16(hv0);
            __nv_bfloat16 hh1 = __float2bfloat16(hv1);
            __nv_bfloat16 hl0 = __float2bfloat16(hv0 - __bfloat162float(hh0));
            __nv_bfloat16 hl1 = __float2bfloat16(hv1 - __bfloat162float(hh1));
            *(uint32_t*)&g_h_hi[ge] =
                (uint32_t)__bfloat16_as_ushort(hh0) | ((uint32_t)__bfloat16_as_ushort(hh1) << 16);
            *(uint32_t*)&g_h_lo[ge] =
                (uint32_t)__bfloat16_as_ushort(hl0) | ((uint32_t)__bfloat16_as_ushort(hl1) << 16);
            *(float2*)&out[((size_t)gn * TT + t) * HH + gj] = make_float2(hv0, hv1);
        }
        grid_sync();
    }
}

// ---------------------------------------------------------------------------
// launch
// ---------------------------------------------------------------------------
extern "C" void kernel_launch(void* const* d_in, const int* in_sizes, int n_in,
                              void* d_out, int out_size) {
    const float* x  = (const float*)d_in[0];
    const float* h0 = (const float*)d_in[1];
    const float* Wx = (const float*)d_in[2];
    const float* Wh = (const float*)d_in[3];
    const float* b  = (const float*)d_in[4];
    float* out = (float*)d_out;

    cudaFuncSetAttribute(xw_mma, cudaFuncAttributeMaxDynamicSharedMemorySize, XW_SMEM);
    cudaFuncSetAttribute(lstm_persistent, cudaFuncAttributeMaxDynamicSharedMemorySize, LSTM_SMEM);

    split_x<<<TT * NN, 256>>>(x);
    split_wx<<<dim3(GG / 32, DD / 32), 256>>>(Wx);
    xw_mma<<<dim3(GG / 128, (TT * NN) / 128), 256, XW_SMEM>>>(b);
    lstm_persistent<<<NBLK, 256, LSTM_SMEM>>>(h0, Wh, out);
}

// round 17
// speedup vs baseline: 1.1508x; 1.1508x over previous
#include <cuda_runtime.h>
#include <cuda_bf16.h>
#include <cstdint>

// Problem dims (fixed by the dataset)
#define TT 512
#define NN 64
#define DD 1024
#define HH 1024
#define GG 4096        // 4*H

#define NBLK 128       // persistent blocks, 1/SM
#define KS 8           // K splits for recurrent GEMM
#define KC (HH / KS)   // 128
#define CGRP 16        // column groups
#define CW (GG / CGRP) // 256 cols per group

// recurrence smem (bytes): Wh^T hi/lo [256][136] bf16 + h hi/lo [64][136] bf16
#define WST 136
#define WHS_HI_OFF 0
#define WHS_LO_OFF (256 * WST * 2)                    // 69632
#define ASH_HI_OFF (2 * 256 * WST * 2)                // 139264
#define ASH_LO_OFF (ASH_HI_OFF + 64 * WST * 2)        // 156672
#define LSTM_SMEM  (ASH_LO_OFF + 64 * WST * 2)        // 174080

// ---- device scratch (allocation-free per harness rules) ----
__device__ float g_xw[(size_t)TT * NN * GG];        // (T*N, 4H) x@Wx + b
__device__ float g_part[KS][NN * GG];               // split-K partials of h@Wh
__device__ __nv_bfloat16 g_h_hi[NN * HH];           // hidden state, hi plane
__device__ __nv_bfloat16 g_h_lo[NN * HH];           // hidden state, lo plane
__device__ unsigned g_count;
__device__ unsigned g_gen;

// bf16 hi/lo split operands for the xW tensor GEMM (k-contiguous rows)
__device__ __nv_bfloat16 g_xa_hi[(size_t)TT * NN * DD];   // A[m][k], m = t*64+n
__device__ __nv_bfloat16 g_xa_lo[(size_t)TT * NN * DD];
__device__ __nv_bfloat16 g_wxt_hi[(size_t)GG * DD];       // B[g][k] = Wx[k][g]
__device__ __nv_bfloat16 g_wxt_lo[(size_t)GG * DD];

// ---------------------------------------------------------------------------
// helpers
// ---------------------------------------------------------------------------
__device__ __forceinline__ float sigm(float x) { return 1.f / (1.f + __expf(-x)); }
__device__ __forceinline__ float tanh_(float x) { return 2.f / (1.f + __expf(-2.f * x)) - 1.f; }

// Flat grid barrier (R14 version — proven fastest)
__device__ __forceinline__ void grid_sync() {
    __syncthreads();
    if (threadIdx.x == 0) {
        unsigned my;
        asm volatile("ld.acquire.gpu.global.u32 %0, [%1];" : "=r"(my) : "l"(&g_gen));
        __threadfence();
        if (atomicAdd(&g_count, 1) == NBLK - 1) {
            atomicExch(&g_count, 0);
            asm volatile("st.release.gpu.global.u32 [%0], %1;" :: "l"(&g_gen), "r"(my + 1));
        } else {
            unsigned cur;
            do {
                asm volatile("ld.acquire.gpu.global.u32 %0, [%1];" : "=r"(cur) : "l"(&g_gen));
            } while (cur == my);
        }
    }
    __syncthreads();
}

__device__ __forceinline__ uint32_t smem_u32(const void* p) {
    uint32_t a;
    asm("{ .reg .u64 t; cvta.to.shared.u64 t, %1; cvt.u32.u64 %0, t; }" : "=r"(a) : "l"(p));
    return a;
}

#define LDSM_X4(r0, r1, r2, r3, addr)                                           \
    asm volatile("ldmatrix.sync.aligned.m8n8.x4.shared.b16 {%0,%1,%2,%3}, [%4];" \
                 : "=r"(r0), "=r"(r1), "=r"(r2), "=r"(r3) : "r"(addr))

#define MMA_BF16(c, a0, a1, a2, a3, b0, b1)                                     \
    asm volatile("mma.sync.aligned.m16n8k16.row.col.f32.bf16.bf16.f32 "         \
                 "{%0,%1,%2,%3},{%4,%5,%6,%7},{%8,%9},{%0,%1,%2,%3};"           \
                 : "+f"(c[0]), "+f"(c[1]), "+f"(c[2]), "+f"(c[3])               \
                 : "r"(a0), "r"(a1), "r"(a2), "r"(a3), "r"(b0), "r"(b1))

#define CP_ASYNC16(dst, src)                                                    \
    asm volatile("cp.async.ca.shared.global [%0], [%1], 16;" :: "r"(dst), "l"(src))
#define CP_COMMIT() asm volatile("cp.async.commit_group;" ::: "memory")
#define CP_WAIT1()  asm volatile("cp.async.wait_group 1;" ::: "memory")
#define CP_WAIT0()  asm volatile("cp.async.wait_group 0;" ::: "memory")

// ---------------------------------------------------------------------------
// split kernels: fp32 -> bf16 hi + bf16 lo  (xW operands)
// ---------------------------------------------------------------------------
__global__ __launch_bounds__(256) void split_x(const float* __restrict__ x) {
    const int m = blockIdx.x;               // m = t*64 + n
    const int t = m >> 6, n = m & 63;
    const float* src = x + ((size_t)n * TT + t) * DD;
    const int d0 = threadIdx.x * 4;
    float4 v = *(const float4*)(src + d0);
    float f[4] = {v.x, v.y, v.z, v.w};
    ushort4 hi, lo;
    unsigned short* hp = &hi.x;
    unsigned short* lp = &lo.x;
    #pragma unroll
    for (int i = 0; i < 4; i++) {
        __nv_bfloat16 h = __float2bfloat16(f[i]);
        __nv_bfloat16 l = __float2bfloat16(f[i] - __bfloat162float(h));
        hp[i] = __bfloat16_as_ushort(h);
        lp[i] = __bfloat16_as_ushort(l);
    }
    size_t o = (size_t)m * DD + d0;
    *(ushort4*)&g_xa_hi[o] = hi;
    *(ushort4*)&g_xa_lo[o] = lo;
}

__global__ __launch_bounds__(256) void split_wx(const float* __restrict__ Wx) {
    __shared__ float tile[32][33];
    const int g0 = blockIdx.x * 32, k0 = blockIdx.y * 32;
    const int tx = threadIdx.x & 31, ty = threadIdx.x >> 5;   // 32 x 8
    #pragma unroll
    for (int j = 0; j < 4; j++)
        tile[ty + j * 8][tx] = Wx[(size_t)(k0 + ty + j * 8) * GG + g0 + tx];
    __syncthreads();
    #pragma unroll
    for (int j = 0; j < 4; j++) {
        float v = tile[tx][ty + j * 8];
        __nv_bfloat16 h = __float2bfloat16(v);
        __nv_bfloat16 l = __float2bfloat16(v - __bfloat162float(h));
        size_t o = (size_t)(g0 + ty + j * 8) * DD + k0 + tx;
        g_wxt_hi[o] = h;
        g_wxt_lo[o] = l;
    }
}

// ---------------------------------------------------------------------------
// xW GEMM on tensor cores (mma.sync bf16, 3-term hi/lo split).
// cp.async double-buffered staging. FIX vs R16: second 16B lands at +16
// bytes (8 bf16), matching R14's so/so+8 element layout.
// ---------------------------------------------------------------------------
#define AST 40
#define XW_ARR  (128 * AST * 2)          // 10240 B per array
#define XW_BUF  (4 * XW_ARR)             // 40960 B per stage buffer
#define XW_SMEM (2 * XW_BUF)             // 81920 B

__global__ __launch_bounds__(256) void xw_mma(const float* __restrict__ b) {
    extern __shared__ char xsm[];
    const uint32_t sb = smem_u32(xsm);

    const int tid = threadIdx.x;
    const int wid = tid >> 5, lane = tid & 31;
    const int m0 = blockIdx.y * 128;
    const int g0 = blockIdx.x * 128;
    const int wm = (wid >> 2) * 64;
    const int wn = (wid & 3) * 32;

    float acc[4][4][4];
    #pragma unroll
    for (int i = 0; i < 4; i++)
        #pragma unroll
        for (int j = 0; j < 4; j++)
            #pragma unroll
            for (int q = 0; q < 4; q++) acc[i][j][q] = 0.f;

    const int sr = tid >> 1;
    const int sh = (tid & 1) * 16;
    const uint32_t so2 = (uint32_t)(sr * AST + sh) * 2;   // byte offset in array

    const uint32_t a_off = (uint32_t)(wm + (lane & 15)) * (AST * 2) + ((lane >> 4) << 4);
    const uint32_t b_off = (uint32_t)(wn + ((lane >> 4) << 3) + (lane & 7)) * (AST * 2)
                           + (((lane >> 3) & 1) << 4);

    const __nv_bfloat16* srcs[4] = {
        g_xa_hi + (size_t)(m0 + sr) * DD + sh,
        g_xa_lo + (size_t)(m0 + sr) * DD + sh,
        g_wxt_hi + (size_t)(g0 + sr) * DD + sh,
        g_wxt_lo + (size_t)(g0 + sr) * DD + sh,
    };

    // issue one 32-k chunk into buffer buf via cp.async (8 x 16B per thread)
    auto issue = [&](int k0, int buf) {
        const uint32_t base = sb + (uint32_t)buf * XW_BUF + so2;
        #pragma unroll
        for (int a = 0; a < 4; a++) {
            CP_ASYNC16(base + a * XW_ARR, srcs[a] + k0);
            CP_ASYNC16(base + a * XW_ARR + 16, srcs[a] + k0 + 8);   // FIX: +16
        }
        CP_COMMIT();
    };

    issue(0, 0);

    for (int i = 0; i < 32; ++i) {
        const int cur = i & 1;
        const bool more = (i + 1 < 32);
        if (more) issue((i + 1) * 32, cur ^ 1);
        if (more) { CP_WAIT1(); } else { CP_WAIT0(); }
        __syncthreads();

        const uint32_t base = sb + (uint32_t)cur * XW_BUF;
        const uint32_t ah_b = base, al_b = base + XW_ARR;
        const uint32_t bh_b = base + 2 * XW_ARR, bl_b = base + 3 * XW_ARR;

        #pragma unroll
        for (int ks = 0; ks < 32; ks += 16) {
            const uint32_t kb = (uint32_t)ks * 2;
            uint32_t bhf[4][2], blf[4][2];
            #pragma unroll
            for (int p = 0; p < 2; p++) {
                uint32_t r0, r1, r2, r3;
                uint32_t off = b_off + (uint32_t)(p * 16) * (AST * 2) + kb;
                LDSM_X4(r0, r1, r2, r3, bh_b + off);
                bhf[2 * p][0] = r0; bhf[2 * p][1] = r1;
                bhf[2 * p + 1][0] = r2; bhf[2 * p + 1][1] = r3;
                LDSM_X4(r0, r1, r2, r3, bl_b + off);
                blf[2 * p][0] = r0; blf[2 * p][1] = r1;
                blf[2 * p + 1][0] = r2; blf[2 * p + 1][1] = r3;
            }
            #pragma unroll
            for (int mt = 0; mt < 4; mt++) {
                uint32_t off = a_off + (uint32_t)(mt * 16) * (AST * 2) + kb;
                uint32_t ah0, ah1, ah2, ah3, al0, al1, al2, al3;
                LDSM_X4(ah0, ah1, ah2, ah3, ah_b + off);
                LDSM_X4(al0, al1, al2, al3, al_b + off);
                #pragma unroll
                for (int nt = 0; nt < 4; nt++) {
                    MMA_BF16(acc[mt][nt], ah0, ah1, ah2, ah3, bhf[nt][0], bhf[nt][1]);
                    MMA_BF16(acc[mt][nt], ah0, ah1, ah2, ah3, blf[nt][0], blf[nt][1]);
                    MMA_BF16(acc[mt][nt], al0, al1, al2, al3, bhf[nt][0], bhf[nt][1]);
                }
            }
        }
        __syncthreads();   // guard buffer reuse
    }

    const int er = lane >> 2;
    const int ec = (lane & 3) * 2;
    #pragma unroll
    for (int mt = 0; mt < 4; mt++) {
        #pragma unroll
        for (int nt = 0; nt < 4; nt++) {
            const int col = g0 + wn + (nt >> 1) * 16 + (nt & 1) * 8 + ec;
            const float2 bias = *(const float2*)&b[col];
            const int row = m0 + wm + mt * 16 + er;
            float2 v0 = make_float2(acc[mt][nt][0] + bias.x, acc[mt][nt][1] + bias.y);
            float2 v1 = make_float2(acc[mt][nt][2] + bias.x, acc[mt][nt][3] + bias.y);
            *(float2*)&g_xw[(size_t)row * GG + col] = v0;
            *(float2*)&g_xw[(size_t)(row + 8) * GG + col] = v1;
        }
    }
}

// ---------------------------------------------------------------------------
// Persistent LSTM recurrence (EXACT R14 kernel — proven 8128us config).
// 128 blocks x 256 threads, 1 CTA/SM. Split-K=8, col-groups=16.
// Wh^T slice SMEM-resident bf16 hi/lo; h in GMEM as bf16 hi/lo planes.
// ---------------------------------------------------------------------------
__global__ void __launch_bounds__(256, 1) lstm_persistent(
    const float* __restrict__ h0,
    const float* __restrict__ Wh,
    float* __restrict__ out) {
    extern __shared__ char smc[];
    __nv_bfloat16* whs_hi = (__nv_bfloat16*)(smc + WHS_HI_OFF);   // [256][WST]
    __nv_bfloat16* whs_lo = (__nv_bfloat16*)(smc + WHS_LO_OFF);
    __nv_bfloat16* ash_hi = (__nv_bfloat16*)(smc + ASH_HI_OFF);   // [64][WST]
    __nv_bfloat16* ash_lo = (__nv_bfloat16*)(smc + ASH_LO_OFF);

    const int tid = threadIdx.x;
    const int blk = blockIdx.x;
    const int wid = tid >> 5, lane = tid & 31;
    const int cg = blk >> 3;           // 0..15 column group
    const int ks = blk & 7;            // 0..7  K split
    const int nc0 = cg * CW;
    const int kbase = ks * KC;
    const int wn = wid * 32;           // warp col offset (8 warps x 32 cols)

    // gate coords: 2 consecutive cells per thread
    const int ge = (blk * 256 + tid) * 2;
    const int gn = ge >> 10;
    const int gj = ge & 1023;

    // ---- one-time: Wh^T slice -> smem bf16 hi/lo, [col][k] stride WST ----
    for (int idx = tid; idx < CW * KC; idx += 256) {
        const int col = idx & 255;
        const int k = idx >> 8;
        float v = Wh[(size_t)(kbase + k) * GG + nc0 + col];
        __nv_bfloat16 h = __float2bfloat16(v);
        __nv_bfloat16 l = __float2bfloat16(v - __bfloat162float(h));
        whs_hi[col * WST + k] = h;
        whs_lo[col * WST + k] = l;
    }

    // ---- init h planes from h0 ----
    {
        float2 v = *(const float2*)&h0[ge];
        __nv_bfloat16 h0a = __float2bfloat16(v.x);
        __nv_bfloat16 h0b = __float2bfloat16(v.y);
        __nv_bfloat16 l0a = __float2bfloat16(v.x - __bfloat162float(h0a));
        __nv_bfloat16 l0b = __float2bfloat16(v.y - __bfloat162float(h0b));
        *(uint32_t*)&g_h_hi[ge] =
            (uint32_t)__bfloat16_as_ushort(h0a) | ((uint32_t)__bfloat16_as_ushort(h0b) << 16);
        *(uint32_t*)&g_h_lo[ge] =
            (uint32_t)__bfloat16_as_ushort(l0a) | ((uint32_t)__bfloat16_as_ushort(l0b) << 16);
    }
    float2 c = make_float2(0.f, 0.f);
    grid_sync();

    // stage coords: row = tid>>2 (0..63), kq = (tid&3)*32 elements
    const int s_row = tid >> 2;
    const int s_kq = (tid & 3) * 32;
    const __nv_bfloat16* hsrc_hi = g_h_hi + (size_t)s_row * HH + kbase + s_kq;
    const __nv_bfloat16* hsrc_lo = g_h_lo + (size_t)s_row * HH + kbase + s_kq;

    // ldmatrix offsets (bytes), stride WST*2 = 272
    const uint32_t ahi_b = smem_u32(ash_hi), alo_b = smem_u32(ash_lo);
    const uint32_t bhi_b = smem_u32(whs_hi), blo_b = smem_u32(whs_lo);
    const uint32_t a_off = (uint32_t)(lane & 15) * (WST * 2) + ((lane >> 4) << 4);
    const uint32_t b_off = (uint32_t)(wn + ((lane >> 4) << 3) + (lane & 7)) * (WST * 2)
                           + (((lane >> 3) & 1) << 4);

    for (int t = 0; t < TT; ++t) {
        // prefetch xw gate values (hidden behind MMA phase)
        float2 xg[4];
        {
            const float* xwt = g_xw + (size_t)t * NN * GG + (size_t)gn * GG + gj;
            #pragma unroll
            for (int g = 0; g < 4; g++) xg[g] = *(const float2*)(xwt + g * HH);
        }

        // ---------- stage: h slice -> smem (pure copy) ----------
        {
            __nv_bfloat16* dh = ash_hi + s_row * WST + s_kq;
            __nv_bfloat16* dl = ash_lo + s_row * WST + s_kq;
            #pragma unroll
            for (int i = 0; i < 4; ++i) {
                *(uint4*)(dh + i * 8) = *(const uint4*)(hsrc_hi + i * 8);
                *(uint4*)(dl + i * 8) = *(const uint4*)(hsrc_lo + i * 8);
            }
        }
        __syncthreads();

        // ---------- MMA phase: 64 x 32(warp) x 128, 3-term split ----------
        float acc[4][4][4];
        #pragma unroll
        for (int i = 0; i < 4; i++)
            #pragma unroll
            for (int j = 0; j < 4; j++)
                #pragma unroll
                for (int q = 0; q < 4; q++) acc[i][j][q] = 0.f;

        #pragma unroll
        for (int kk = 0; kk < 8; ++kk) {
            const uint32_t kb = (uint32_t)kk * 32;
            uint32_t bhf[4][2], blf[4][2];
            #pragma unroll
            for (int p = 0; p < 2; p++) {
                uint32_t r0, r1, r2, r3;
                uint32_t off = b_off + (uint32_t)(p * 16) * (WST * 2) + kb;
                LDSM_X4(r0, r1, r2, r3, bhi_b + off);
                bhf[2 * p][0] = r0; bhf[2 * p][1] = r1;
                bhf[2 * p + 1][0] = r2; bhf[2 * p + 1][1] = r3;
                LDSM_X4(r0, r1, r2, r3, blo_b + off);
                blf[2 * p][0] = r0; blf[2 * p][1] = r1;
                blf[2 * p + 1][0] = r2; blf[2 * p + 1][1] = r3;
            }
            #pragma unroll
            for (int mt = 0; mt < 4; mt++) {
                uint32_t off = a_off + (uint32_t)(mt * 16) * (WST * 2) + kb;
                uint32_t ah0, ah1, ah2, ah3, al0, al1, al2, al3;
                LDSM_X4(ah0, ah1, ah2, ah3, ahi_b + off);
                LDSM_X4(al0, al1, al2, al3, alo_b + off);
                #pragma unroll
                for (int nt = 0; nt < 4; nt++) {
                    MMA_BF16(acc[mt][nt], ah0, ah1, ah2, ah3, bhf[nt][0], bhf[nt][1]);
                    MMA_BF16(acc[mt][nt], ah0, ah1, ah2, ah3, blf[nt][0], blf[nt][1]);
                    MMA_BF16(acc[mt][nt], al0, al1, al2, al3, bhf[nt][0], bhf[nt][1]);
                }
            }
        }
        __syncthreads();   // ash reuse next step

        // ---------- store partial tile ----------
        {
            float* dst = g_part[ks];
            const int er = lane >> 2;
            const int ec = (lane & 3) * 2;
            #pragma unroll
            for (int mt = 0; mt < 4; mt++) {
                #pragma unroll
                for (int nt = 0; nt < 4; nt++) {
                    const int col = nc0 + wn + (nt >> 1) * 16 + (nt & 1) * 8 + ec;
                    const int row = mt * 16 + er;
                    *(float2*)&dst[(size_t)row * GG + col] =
                        make_float2(acc[mt][nt][0], acc[mt][nt][1]);
                    *(float2*)&dst[(size_t)(row + 8) * GG + col] =
                        make_float2(acc[mt][nt][2], acc[mt][nt][3]);
                }
            }
        }
        grid_sync();

        // ---------- gates: 2 cells per thread ----------
        {
            size_t bi = (size_t)gn * GG + gj;
            float2 pi = xg[0], pf = xg[1], po = xg[2], pg = xg[3];
            #pragma unroll
            for (int s = 0; s < KS; ++s) {
                const float* p = g_part[s];
                float2 v;
                v = *(const float2*)&p[bi];          pi.x += v.x; pi.y += v.y;
                v = *(const float2*)&p[bi + HH];     pf.x += v.x; pf.y += v.y;
                v = *(const float2*)&p[bi + 2 * HH]; po.x += v.x; po.y += v.y;
                v = *(const float2*)&p[bi + 3 * HH]; pg.x += v.x; pg.y += v.y;
            }
            float i0 = sigm(pi.x), f0 = sigm(pf.x), o0 = sigm(po.x), q0 = tanh_(pg.x);
            float i1 = sigm(pi.y), f1 = sigm(pf.y), o1 = sigm(po.y), q1 = tanh_(pg.y);
            c.x = f0 * c.x + i0 * q0;
            c.y = f1 * c.y + i1 * q1;
            float hv0 = o0 * tanh_(c.x);
            float hv1 = o1 * tanh_(c.y);

            __nv_bfloat16 hh0 = __float2bfloat16(hv0);
            __nv_bfloat16 hh1 = __float2bfloat16(hv1);
            __nv_bfloat16 hl0 = __float2bfloat16(hv0 - __bfloat162float(hh0));
            __nv_bfloat16 hl1 = __float2bfloat16(hv1 - __bfloat162float(hh1));
            *(uint32_t*)&g_h_hi[ge] =
                (uint32_t)__bfloat16_as_ushort(hh0) | ((uint32_t)__bfloat16_as_ushort(hh1) << 16);
            *(uint32_t*)&g_h_lo[ge] =
                (uint32_t)__bfloat16_as_ushort(hl0) | ((uint32_t)__bfloat16_as_ushort(hl1) << 16);
            *(float2*)&out[((size_t)gn * TT + t) * HH + gj] = make_float2(hv0, hv1);
        }
        grid_sync();
    }
}

// ---------------------------------------------------------------------------
// launch
// ---------------------------------------------------------------------------
extern "C" void kernel_launch(void* const* d_in, const int* in_sizes, int n_in,
                              void* d_out, int out_size) {
    const float* x  = (const float*)d_in[0];
    const float* h0 = (const float*)d_in[1];
    const float* Wx = (const float*)d_in[2];
    const float* Wh = (const float*)d_in[3];
    const float* b  = (const float*)d_in[4];
    float* out = (float*)d_out;

    cudaFuncSetAttribute(xw_mma, cudaFuncAttributeMaxDynamicSharedMemorySize, XW_SMEM);
    cudaFuncSetAttribute(lstm_persistent, cudaFuncAttributeMaxDynamicSharedMemorySize, LSTM_SMEM);

    split_x<<<TT * NN, 256>>>(x);
    split_wx<<<dim3(GG / 32, DD / 32), 256>>>(Wx);
    xw_mma<<<dim3(GG / 128, (TT * NN) / 128), 256, XW_SMEM>>>(b);
    lstm_persistent<<<NBLK, 256, LSTM_SMEM>>>(h0, Wh, out);
}